// round 7
// baseline (speedup 1.0000x reference)
#include <cuda_runtime.h>
#include <cuda_bf16.h>
#include <cuda_fp16.h>
#include <cstdint>
#include <cstddef>

#define N_NODES 100000
#define N_EDGES 1600000
#define IN_DIM  256
#define OUT_DIM 128

// ---------------- scratch (no cudaMalloc allowed) ----------------
__device__ __half g_h16[(size_t)N_NODES * OUT_DIM]; // h (unscaled, fp16)  (25.6 MB)
__device__ uint4 g_wcbh[4096];                      // Wc hi bf16, [ch][n][k] packed
__device__ uint4 g_wcbl[4096];                      // Wc lo bf16
__device__ float g_dinv[N_NODES];                   // 1/sqrt(deg)
__device__ int   g_cnt[N_NODES];                    // in-degree (edges only)
__device__ int   g_cur[N_NODES];                    // scatter cursors
__device__ int   g_rowptr[N_NODES + 1];             // CSR row pointers (by target)
__device__ int   g_srcs[N_EDGES];                   // sorted-by-target source ids
__device__ int   g_incl[N_NODES];                   // per-chunk inclusive scans
__device__ int   g_bsum[512];                       // block sums for scan
__device__ int   g_is64;                            // edge_index dtype flag

// ---------------- dtype detection (int64 vs int32 edge_index) ----------------
__global__ void detect_kernel(const void* __restrict__ ei) {
    if (threadIdx.x == 0 && blockIdx.x == 0) {
        const long long* p = (const long long*)ei;
        int is64 = 1;
        for (int i = 0; i < 8; i++) {
            long long v = p[i];
            if (v < 0 || v >= N_NODES) { is64 = 0; break; }
        }
        g_is64 = is64;
    }
}

__device__ __forceinline__ int load_idx(const void* __restrict__ ei, long long i, int is64) {
    if (is64) return (int)((const long long*)ei)[i];
    return ((const int*)ei)[i];
}

// ---------------- Wc = Wg @ Wp, split to packed bf16 hi/lo (rn split) ----------
__global__ void wc_kernel(const float* __restrict__ Wp, const float* __restrict__ Wg) {
    __shared__ float sWg[OUT_DIM];
    const int o2 = blockIdx.x;     // 0..127 (output row n)
    const int i  = threadIdx.x;    // 0..255 (k)
    if (i < OUT_DIM) sWg[i] = Wg[o2 * OUT_DIM + i];
    __syncthreads();
    float acc = 0.f;
#pragma unroll 8
    for (int o = 0; o < OUT_DIM; o++)
        acc += sWg[o] * Wp[o * IN_DIM + i];
    __nv_bfloat16 hi = __float2bfloat16_rn(acc);
    __nv_bfloat16 lo = __float2bfloat16_rn(acc - __bfloat162float(hi));
    int idx = (i >> 5) * 4096 + o2 * 32 + (i & 31);
    ((__nv_bfloat16*)g_wcbh)[idx] = hi;
    ((__nv_bfloat16*)g_wcbl)[idx] = lo;
}

// ---------------- CSR build ----------------
__global__ void zero_cnt_kernel(int nN) {
    int i = blockIdx.x * blockDim.x + threadIdx.x;
    if (i < nN) g_cnt[i] = 0;
}

__global__ void hist_kernel(const void* __restrict__ ei, int nE) {
    int e = blockIdx.x * blockDim.x + threadIdx.x;
    if (e >= nE) return;
    int c = load_idx(ei, (long long)nE + e, g_is64);   // col (target)
    atomicAdd(&g_cnt[c], 1);
}

__global__ void scanA_kernel(int nN) {
    __shared__ int s[256];
    int tid = threadIdx.x;
    int i = blockIdx.x * 256 + tid;
    int v = (i < nN) ? g_cnt[i] : 0;
    s[tid] = v;
    __syncthreads();
#pragma unroll
    for (int o = 1; o < 256; o <<= 1) {
        int t = (tid >= o) ? s[tid - o] : 0;
        __syncthreads();
        s[tid] += t;
        __syncthreads();
    }
    if (i < nN) g_incl[i] = s[tid];
    if (tid == 255) g_bsum[blockIdx.x] = s[255];
}

__global__ void scanB_kernel(int nb) {
    __shared__ int s[512];
    int tid = threadIdx.x;
    int v = (tid < nb) ? g_bsum[tid] : 0;
    s[tid] = v;
    __syncthreads();
#pragma unroll
    for (int o = 1; o < 512; o <<= 1) {
        int t = (tid >= o) ? s[tid - o] : 0;
        __syncthreads();
        s[tid] += t;
        __syncthreads();
    }
    if (tid < nb) g_bsum[tid] = s[tid] - v;   // exclusive
}

__global__ void scanC_kernel(int nN, int nE) {
    int i = blockIdx.x * blockDim.x + threadIdx.x;
    if (i >= nN) return;
    int incl = g_incl[i] + g_bsum[i >> 8];
    g_rowptr[i + 1] = incl;
    int cnt = g_cnt[i];
    g_cur[i] = incl - cnt;                    // exclusive offset
    g_dinv[i] = rsqrtf((float)(cnt + 1));     // +1 for self loop
    if (i == 0) g_rowptr[0] = 0;
}

__global__ void permute_kernel(const void* __restrict__ ei, int nE) {
    int e = blockIdx.x * blockDim.x + threadIdx.x;
    if (e >= nE) return;
    int is64 = g_is64;
    int r = load_idx(ei, e, is64);                     // row (source)
    int c = load_idx(ei, (long long)nE + e, is64);     // col (target)
    int p = atomicAdd(&g_cur[c], 1);
    g_srcs[p] = r;
}

// ---------------- GEMM via mma.sync bf16 split: h = x @ Wc^T (unscaled) --------
// CTA tile 128(M) x 128(N), K=256 in chunks of 32. 8 warps = 4(M) x 2(N).
// Warp tile 32x64. D += Ah*Bh + Ah*Bl + Al*Bh. A global loads ping-pong prefetched.
#define KC 32
#define SROW 20   // uint32 (bf16x2) per smem row: 16 data + 4 pad (80B stride)

__device__ __forceinline__ void mma_bf16(float* c, const uint32_t* a, uint32_t b0, uint32_t b1) {
    asm volatile(
        "mma.sync.aligned.m16n8k16.row.col.f32.bf16.bf16.f32 "
        "{%0,%1,%2,%3}, {%4,%5,%6,%7}, {%8,%9}, {%0,%1,%2,%3};"
        : "+f"(c[0]), "+f"(c[1]), "+f"(c[2]), "+f"(c[3])
        : "r"(a[0]), "r"(a[1]), "r"(a[2]), "r"(a[3]), "r"(b0), "r"(b1));
}

// truncation split of (x, y): hi packed via PRMT, lo = rn(x - hi_f32)
__device__ __forceinline__ uint32_t trunc_split(float x, float y, uint32_t& lo) {
    uint32_t ux = __float_as_uint(x);
    uint32_t uy = __float_as_uint(y);
    uint32_t hiP = __byte_perm(ux, uy, 0x7632);          // [x_hi16 | y_hi16]
    float hx = __uint_as_float(ux & 0xffff0000u);
    float hy = __uint_as_float(uy & 0xffff0000u);
    __nv_bfloat162 l2 = __floats2bfloat162_rn(x - hx, y - hy);  // x->low, y->high
    lo = *(uint32_t*)&l2;
    return hiP;
}

__device__ __forceinline__ void loadA_regs(const float* __restrict__ x, int m0, int kk,
                                           int tid, int nN, float4* av) {
#pragma unroll
    for (int i = 0; i < 4; i++) {
        int idx = tid + i * 256;
        int row = idx >> 3;
        int q   = idx & 7;
        int gm  = m0 + row;
        av[i] = make_float4(0.f, 0.f, 0.f, 0.f);
        if (gm < nN) av[i] = __ldg((const float4*)(x + (size_t)gm * IN_DIM + kk + q * 4));
    }
}

__global__ void __launch_bounds__(256) gemm_mma_kernel(const float* __restrict__ x, int nN) {
    __shared__ __align__(16) uint32_t saH[128 * SROW];
    __shared__ __align__(16) uint32_t saL[128 * SROW];
    __shared__ __align__(16) uint32_t sbH[128 * SROW];
    __shared__ __align__(16) uint32_t sbL[128 * SROW];

    const int tid  = threadIdx.x;
    const int wid  = tid >> 5;
    const int lane = tid & 31;
    const int g    = lane >> 2;   // groupID
    const int tg   = lane & 3;    // thread in group
    const int wm   = wid >> 1;    // 0..3  -> m offset 32*wm
    const int wn   = wid & 1;     // 0..1  -> n offset 64*wn
    const int m0   = blockIdx.x * 128;

    float acc[2][8][4];
#pragma unroll
    for (int mt = 0; mt < 2; mt++)
#pragma unroll
        for (int nt = 0; nt < 8; nt++)
#pragma unroll
            for (int j = 0; j < 4; j++) acc[mt][nt][j] = 0.f;

    float4 av[2][4];
    loadA_regs(x, m0, 0, tid, nN, av[0]);

#pragma unroll 2
    for (int ch = 0; ch < IN_DIM / KC; ch++) {
        const int cur = ch & 1;
        // stage A from registers (convert trunc split)
#pragma unroll
        for (int i = 0; i < 4; i++) {
            int idx = tid + i * 256;
            int row = idx >> 3;
            int q   = idx & 7;
            float4 v = av[cur][i];
            uint32_t l0, l1;
            uint32_t h0 = trunc_split(v.x, v.y, l0);
            uint32_t h1 = trunc_split(v.z, v.w, l1);
            int o = row * SROW + q * 2;
            saH[o] = h0; saH[o + 1] = h1;
            saL[o] = l0; saL[o + 1] = l1;
        }
        // stage B: raw copy of pre-converted bf16 hi/lo
        {
            const uint4* bh = g_wcbh + ch * 512;
            const uint4* bl = g_wcbl + ch * 512;
#pragma unroll
            for (int i = 0; i < 2; i++) {
                int idx = tid + i * 256;
                int n   = idx >> 2;
                int qq  = idx & 3;
                *(uint4*)&sbH[n * SROW + qq * 4] = __ldg(&bh[idx]);
                *(uint4*)&sbL[n * SROW + qq * 4] = __ldg(&bl[idx]);
            }
        }
        // prefetch next chunk's A while MMAs run
        if (ch + 1 < IN_DIM / KC)
            loadA_regs(x, m0, (ch + 1) * KC, tid, nN, av[cur ^ 1]);
        __syncthreads();

#pragma unroll
        for (int ks = 0; ks < KC / 16; ks++) {
            uint32_t aH[2][4], aL[2][4];
#pragma unroll
            for (int mt = 0; mt < 2; mt++) {
                int rbase = (wm * 32 + mt * 16) * SROW + ks * 8;
                aH[mt][0] = saH[rbase + g * SROW + tg];
                aH[mt][1] = saH[rbase + (g + 8) * SROW + tg];
                aH[mt][2] = saH[rbase + g * SROW + tg + 4];
                aH[mt][3] = saH[rbase + (g + 8) * SROW + tg + 4];
                aL[mt][0] = saL[rbase + g * SROW + tg];
                aL[mt][1] = saL[rbase + (g + 8) * SROW + tg];
                aL[mt][2] = saL[rbase + g * SROW + tg + 4];
                aL[mt][3] = saL[rbase + (g + 8) * SROW + tg + 4];
            }
#pragma unroll
            for (int nt = 0; nt < 8; nt++) {
                int n = wn * 64 + nt * 8 + g;
                int o = n * SROW + ks * 8 + tg;
                uint32_t bH0 = sbH[o], bH1 = sbH[o + 4];
                uint32_t bL0 = sbL[o], bL1 = sbL[o + 4];
#pragma unroll
                for (int mt = 0; mt < 2; mt++) {
                    mma_bf16(acc[mt][nt], aH[mt], bH0, bH1);
                    mma_bf16(acc[mt][nt], aH[mt], bL0, bL1);
                    mma_bf16(acc[mt][nt], aL[mt], bH0, bH1);
                }
            }
        }
        __syncthreads();
    }

    // epilogue: store h (unscaled) as fp16
#pragma unroll
    for (int mt = 0; mt < 2; mt++) {
        int r0 = m0 + wm * 32 + mt * 16 + g;
        int r1 = r0 + 8;
#pragma unroll
        for (int nt = 0; nt < 8; nt++) {
            int col = wn * 64 + nt * 8 + tg * 2;
            if (r0 < nN) {
                __half2 o = __floats2half2_rn(acc[mt][nt][0], acc[mt][nt][1]);
                *(__half2*)(g_h16 + (size_t)r0 * OUT_DIM + col) = o;
            }
            if (r1 < nN) {
                __half2 o = __floats2half2_rn(acc[mt][nt][2], acc[mt][nt][3]);
                *(__half2*)(g_h16 + (size_t)r1 * OUT_DIM + col) = o;
            }
        }
    }
}

// ---------------- fused aggregate + finalize (half-warp per node, fp16 gather) ---
__device__ __forceinline__ void acc8(float* a, uint4 raw, float d) {
    __half2* h = (__half2*)&raw;
#pragma unroll
    for (int j = 0; j < 4; j++) {
        float2 f = __half22float2(h[j]);
        a[j * 2]     += f.x * d;
        a[j * 2 + 1] += f.y * d;
    }
}

__global__ void __launch_bounds__(256) aggregate_kernel(
    float* __restrict__ out, const float* __restrict__ bg, int nN) {
    int gw   = (int)((blockIdx.x * (unsigned)blockDim.x + threadIdx.x) >> 5);
    int lane = threadIdx.x & 31;
    int half = lane >> 4;          // 0/1: which node this half-warp owns
    int sl   = lane & 15;          // sublane within half-warp
    int node = gw * 2 + half;
    if (node >= nN) return;

    int beg = g_rowptr[node];
    int end = g_rowptr[node + 1];
    float dw = g_dinv[node];

    float a[8] = {0.f, 0.f, 0.f, 0.f, 0.f, 0.f, 0.f, 0.f};
    // self loop
    {
        uint4 r = __ldg(&((const uint4*)(g_h16 + (size_t)node * OUT_DIM))[sl]);
        acc8(a, r, dw);
    }

    int e = beg;
    for (; e + 4 <= end; e += 4) {
        int s0 = __ldg(&g_srcs[e + 0]);
        int s1 = __ldg(&g_srcs[e + 1]);
        int s2 = __ldg(&g_srcs[e + 2]);
        int s3 = __ldg(&g_srcs[e + 3]);
        uint4 r0 = __ldg(&((const uint4*)(g_h16 + (size_t)s0 * OUT_DIM))[sl]);
        uint4 r1 = __ldg(&((const uint4*)(g_h16 + (size_t)s1 * OUT_DIM))[sl]);
        uint4 r2 = __ldg(&((const uint4*)(g_h16 + (size_t)s2 * OUT_DIM))[sl]);
        uint4 r3 = __ldg(&((const uint4*)(g_h16 + (size_t)s3 * OUT_DIM))[sl]);
        float d0 = __ldg(&g_dinv[s0]);
        float d1 = __ldg(&g_dinv[s1]);
        float d2 = __ldg(&g_dinv[s2]);
        float d3 = __ldg(&g_dinv[s3]);
        acc8(a, r0, d0);
        acc8(a, r1, d1);
        acc8(a, r2, d2);
        acc8(a, r3, d3);
    }
    for (; e < end; e++) {
        int s0 = __ldg(&g_srcs[e]);
        uint4 r0 = __ldg(&((const uint4*)(g_h16 + (size_t)s0 * OUT_DIM))[sl]);
        float d0 = __ldg(&g_dinv[s0]);
        acc8(a, r0, d0);
    }

    // bias + dinv scale
    float4 b0 = ((const float4*)bg)[sl * 2];
    float4 b1 = ((const float4*)bg)[sl * 2 + 1];
    a[0] = a[0] * dw + b0.x;  a[1] = a[1] * dw + b0.y;
    a[2] = a[2] * dw + b0.z;  a[3] = a[3] * dw + b0.w;
    a[4] = a[4] * dw + b1.x;  a[5] = a[5] * dw + b1.y;
    a[6] = a[6] * dw + b1.z;  a[7] = a[7] * dw + b1.w;

    float ss = 0.f;
#pragma unroll
    for (int j = 0; j < 8; j++) ss += a[j] * a[j];
#pragma unroll
    for (int o = 8; o > 0; o >>= 1) ss += __shfl_xor_sync(0xffffffffu, ss, o);
    float inv = 1.0f / fmaxf(sqrtf(ss), 1e-12f);

    float* dst = out + (size_t)node * OUT_DIM + sl * 8;
    *(float4*)(dst)     = make_float4(a[0] * inv, a[1] * inv, a[2] * inv, a[3] * inv);
    *(float4*)(dst + 4) = make_float4(a[4] * inv, a[5] * inv, a[6] * inv, a[7] * inv);
}

// ---------------- launch (stream fork/join, capture-legal) ----------------
extern "C" void kernel_launch(void* const* d_in, const int* in_sizes, int n_in,
                              void* d_out, int out_size) {
    const float* x  = (const float*)d_in[0];
    const void*  ei = d_in[1];
    const float* Wp = (const float*)d_in[2];
    const float* Wg = (const float*)d_in[3];
    const float* bg = (const float*)d_in[4];
    float* out = (float*)d_out;

    const int nN = in_sizes[0] / IN_DIM;   // 100000
    const int nE = in_sizes[1] / 2;        // 1600000
    const int nScanBlocks = (nN + 255) / 256;

    static cudaStream_t s2;
    static cudaEvent_t evF, evJ;
    static bool inited = false;
    if (!inited) {
        cudaStreamCreateWithFlags(&s2, cudaStreamNonBlocking);
        cudaEventCreateWithFlags(&evF, cudaEventDisableTiming);
        cudaEventCreateWithFlags(&evJ, cudaEventDisableTiming);
        inited = true;
    }

    // fork: CSR chain on s2, GEMM chain on default stream
    cudaEventRecord(evF, 0);
    cudaStreamWaitEvent(s2, evF, 0);

    detect_kernel<<<1, 32, 0, s2>>>(ei);
    zero_cnt_kernel<<<(nN + 255) / 256, 256, 0, s2>>>(nN);
    hist_kernel<<<(nE + 255) / 256, 256, 0, s2>>>(ei, nE);
    scanA_kernel<<<nScanBlocks, 256, 0, s2>>>(nN);
    scanB_kernel<<<1, 512, 0, s2>>>(nScanBlocks);
    scanC_kernel<<<(nN + 255) / 256, 256, 0, s2>>>(nN, nE);
    permute_kernel<<<(nE + 255) / 256, 256, 0, s2>>>(ei, nE);
    cudaEventRecord(evJ, s2);

    wc_kernel<<<OUT_DIM, 256>>>(Wp, Wg);
    gemm_mma_kernel<<<(nN + 127) / 128, 256>>>(x, nN);

    // join
    cudaStreamWaitEvent(0, evJ, 0);

    int warps = (nN + 1) / 2;
    int agg_blocks = (warps * 32 + 255) / 256;
    aggregate_kernel<<<agg_blocks, 256>>>(out, bg, nN);
}

// round 8
// speedup vs baseline: 1.2176x; 1.2176x over previous
#include <cuda_runtime.h>
#include <cuda_bf16.h>
#include <cuda_fp16.h>
#include <cstdint>
#include <cstddef>

#define N_NODES 100000
#define N_EDGES 1600000
#define IN_DIM  256
#define OUT_DIM 128

// ---------------- scratch (no cudaMalloc allowed) ----------------
__device__ __half g_h16[(size_t)N_NODES * OUT_DIM]; // h (unscaled, fp16)  (25.6 MB)
__device__ uint4 g_wcbh[4096];                      // Wc hi bf16, [ch][n][k] packed
__device__ uint4 g_wcbl[4096];                      // Wc lo bf16
__device__ float g_dinv[N_NODES];                   // 1/sqrt(deg)
__device__ int   g_cnt[N_NODES];                    // in-degree (edges only)
__device__ int   g_cur[N_NODES];                    // scatter cursors
__device__ int   g_rowptr[N_NODES + 1];             // CSR row pointers (by target)
__device__ int   g_srcs[N_EDGES];                   // sorted-by-target source ids
__device__ int   g_incl[N_NODES];                   // per-chunk inclusive scans
__device__ int   g_bsum[512];                       // block sums for scan
__device__ int   g_is64;                            // edge_index dtype flag

// ---------------- dtype detection (int64 vs int32 edge_index) ----------------
__global__ void detect_kernel(const void* __restrict__ ei) {
    if (threadIdx.x == 0 && blockIdx.x == 0) {
        const long long* p = (const long long*)ei;
        int is64 = 1;
        for (int i = 0; i < 8; i++) {
            long long v = p[i];
            if (v < 0 || v >= N_NODES) { is64 = 0; break; }
        }
        g_is64 = is64;
    }
}

__device__ __forceinline__ int load_idx(const void* __restrict__ ei, long long i, int is64) {
    if (is64) return (int)((const long long*)ei)[i];
    return ((const int*)ei)[i];
}

// ---------------- Wc = Wg @ Wp, split to packed bf16 hi/lo (rn split) ----------
__global__ void wc_kernel(const float* __restrict__ Wp, const float* __restrict__ Wg) {
    __shared__ float sWg[OUT_DIM];
    const int o2 = blockIdx.x;     // 0..127 (output row n)
    const int i  = threadIdx.x;    // 0..255 (k)
    if (i < OUT_DIM) sWg[i] = Wg[o2 * OUT_DIM + i];
    __syncthreads();
    float acc = 0.f;
#pragma unroll 8
    for (int o = 0; o < OUT_DIM; o++)
        acc += sWg[o] * Wp[o * IN_DIM + i];
    __nv_bfloat16 hi = __float2bfloat16_rn(acc);
    __nv_bfloat16 lo = __float2bfloat16_rn(acc - __bfloat162float(hi));
    int idx = (i >> 5) * 4096 + o2 * 32 + (i & 31);
    ((__nv_bfloat16*)g_wcbh)[idx] = hi;
    ((__nv_bfloat16*)g_wcbl)[idx] = lo;
}

// ---------------- CSR build ----------------
__global__ void zero_cnt_kernel(int nN) {
    int i = blockIdx.x * blockDim.x + threadIdx.x;
    if (i < nN) g_cnt[i] = 0;
}

__global__ void hist_kernel(const void* __restrict__ ei, int nE) {
    int e = blockIdx.x * blockDim.x + threadIdx.x;
    if (e >= nE) return;
    int c = load_idx(ei, (long long)nE + e, g_is64);   // col (target)
    atomicAdd(&g_cnt[c], 1);
}

__global__ void scanA_kernel(int nN) {
    __shared__ int s[256];
    int tid = threadIdx.x;
    int i = blockIdx.x * 256 + tid;
    int v = (i < nN) ? g_cnt[i] : 0;
    s[tid] = v;
    __syncthreads();
#pragma unroll
    for (int o = 1; o < 256; o <<= 1) {
        int t = (tid >= o) ? s[tid - o] : 0;
        __syncthreads();
        s[tid] += t;
        __syncthreads();
    }
    if (i < nN) g_incl[i] = s[tid];
    if (tid == 255) g_bsum[blockIdx.x] = s[255];
}

__global__ void scanB_kernel(int nb) {
    __shared__ int s[512];
    int tid = threadIdx.x;
    int v = (tid < nb) ? g_bsum[tid] : 0;
    s[tid] = v;
    __syncthreads();
#pragma unroll
    for (int o = 1; o < 512; o <<= 1) {
        int t = (tid >= o) ? s[tid - o] : 0;
        __syncthreads();
        s[tid] += t;
        __syncthreads();
    }
    if (tid < nb) g_bsum[tid] = s[tid] - v;   // exclusive
}

__global__ void scanC_kernel(int nN, int nE) {
    int i = blockIdx.x * blockDim.x + threadIdx.x;
    if (i >= nN) return;
    int incl = g_incl[i] + g_bsum[i >> 8];
    g_rowptr[i + 1] = incl;
    int cnt = g_cnt[i];
    g_cur[i] = incl - cnt;                    // exclusive offset
    g_dinv[i] = rsqrtf((float)(cnt + 1));     // +1 for self loop
    if (i == 0) g_rowptr[0] = 0;
}

__global__ void permute_kernel(const void* __restrict__ ei, int nE) {
    int e = blockIdx.x * blockDim.x + threadIdx.x;
    if (e >= nE) return;
    int is64 = g_is64;
    int r = load_idx(ei, e, is64);                     // row (source)
    int c = load_idx(ei, (long long)nE + e, is64);     // col (target)
    int p = atomicAdd(&g_cur[c], 1);
    g_srcs[p] = r;
}

// ---------------- GEMM via mma.sync bf16 split: h = x @ Wc^T (unscaled) --------
// CTA tile 128(M) x 128(N), K=256 in chunks of 32. 8 warps = 4(M) x 2(N).
// Warp tile 32x64. D += Ah*Bh + Ah*Bl + Al*Bh. (round-6 config: no reg prefetch)
#define KC 32
#define SROW 20   // uint32 (bf16x2) per smem row: 16 data + 4 pad (80B stride)

__device__ __forceinline__ void mma_bf16(float* c, const uint32_t* a, uint32_t b0, uint32_t b1) {
    asm volatile(
        "mma.sync.aligned.m16n8k16.row.col.f32.bf16.bf16.f32 "
        "{%0,%1,%2,%3}, {%4,%5,%6,%7}, {%8,%9}, {%0,%1,%2,%3};"
        : "+f"(c[0]), "+f"(c[1]), "+f"(c[2]), "+f"(c[3])
        : "r"(a[0]), "r"(a[1]), "r"(a[2]), "r"(a[3]), "r"(b0), "r"(b1));
}

// truncation split of (x, y): hi packed via PRMT, lo = rn(x - hi_f32)
__device__ __forceinline__ uint32_t trunc_split(float x, float y, uint32_t& lo) {
    uint32_t ux = __float_as_uint(x);
    uint32_t uy = __float_as_uint(y);
    uint32_t hiP = __byte_perm(ux, uy, 0x7632);          // [x_hi16 | y_hi16]
    float hx = __uint_as_float(ux & 0xffff0000u);
    float hy = __uint_as_float(uy & 0xffff0000u);
    __nv_bfloat162 l2 = __floats2bfloat162_rn(x - hx, y - hy);  // x->low, y->high
    lo = *(uint32_t*)&l2;
    return hiP;
}

__global__ void __launch_bounds__(256) gemm_mma_kernel(const float* __restrict__ x, int nN) {
    __shared__ __align__(16) uint32_t saH[128 * SROW];
    __shared__ __align__(16) uint32_t saL[128 * SROW];
    __shared__ __align__(16) uint32_t sbH[128 * SROW];
    __shared__ __align__(16) uint32_t sbL[128 * SROW];

    const int tid  = threadIdx.x;
    const int wid  = tid >> 5;
    const int lane = tid & 31;
    const int g    = lane >> 2;   // groupID
    const int tg   = lane & 3;    // thread in group
    const int wm   = wid >> 1;    // 0..3  -> m offset 32*wm
    const int wn   = wid & 1;     // 0..1  -> n offset 64*wn
    const int m0   = blockIdx.x * 128;

    float acc[2][8][4];
#pragma unroll
    for (int mt = 0; mt < 2; mt++)
#pragma unroll
        for (int nt = 0; nt < 8; nt++)
#pragma unroll
            for (int j = 0; j < 4; j++) acc[mt][nt][j] = 0.f;

    for (int ch = 0; ch < IN_DIM / KC; ch++) {
        const int kk = ch * KC;
        // stage A (x rows, f32 -> bf16 hi/lo via trunc split) : 128 x 32
#pragma unroll
        for (int i = 0; i < 4; i++) {
            int idx = tid + i * 256;
            int row = idx >> 3;          // 0..127
            int q   = idx & 7;           // float4 index within 32 k
            int gm  = m0 + row;
            float4 v = make_float4(0.f, 0.f, 0.f, 0.f);
            if (gm < nN) v = __ldg((const float4*)(x + (size_t)gm * IN_DIM + kk + q * 4));
            uint32_t l0, l1;
            uint32_t h0 = trunc_split(v.x, v.y, l0);
            uint32_t h1 = trunc_split(v.z, v.w, l1);
            int o = row * SROW + q * 2;
            saH[o] = h0; saH[o + 1] = h1;
            saL[o] = l0; saL[o + 1] = l1;
        }
        // stage B: raw copy of pre-converted bf16 hi/lo (512 uint4 per buffer)
        {
            const uint4* bh = g_wcbh + ch * 512;
            const uint4* bl = g_wcbl + ch * 512;
#pragma unroll
            for (int i = 0; i < 2; i++) {
                int idx = tid + i * 256;
                int n   = idx >> 2;
                int qq  = idx & 3;
                *(uint4*)&sbH[n * SROW + qq * 4] = __ldg(&bh[idx]);
                *(uint4*)&sbL[n * SROW + qq * 4] = __ldg(&bl[idx]);
            }
        }
        __syncthreads();

#pragma unroll
        for (int ks = 0; ks < KC / 16; ks++) {
            uint32_t aH[2][4], aL[2][4];
#pragma unroll
            for (int mt = 0; mt < 2; mt++) {
                int rbase = (wm * 32 + mt * 16) * SROW + ks * 8;
                aH[mt][0] = saH[rbase + g * SROW + tg];
                aH[mt][1] = saH[rbase + (g + 8) * SROW + tg];
                aH[mt][2] = saH[rbase + g * SROW + tg + 4];
                aH[mt][3] = saH[rbase + (g + 8) * SROW + tg + 4];
                aL[mt][0] = saL[rbase + g * SROW + tg];
                aL[mt][1] = saL[rbase + (g + 8) * SROW + tg];
                aL[mt][2] = saL[rbase + g * SROW + tg + 4];
                aL[mt][3] = saL[rbase + (g + 8) * SROW + tg + 4];
            }
#pragma unroll
            for (int nt = 0; nt < 8; nt++) {
                int n = wn * 64 + nt * 8 + g;
                int o = n * SROW + ks * 8 + tg;
                uint32_t bH0 = sbH[o], bH1 = sbH[o + 4];
                uint32_t bL0 = sbL[o], bL1 = sbL[o + 4];
#pragma unroll
                for (int mt = 0; mt < 2; mt++) {
                    mma_bf16(acc[mt][nt], aH[mt], bH0, bH1);
                    mma_bf16(acc[mt][nt], aH[mt], bL0, bL1);
                    mma_bf16(acc[mt][nt], aL[mt], bH0, bH1);
                }
            }
        }
        __syncthreads();
    }

    // epilogue: store h (unscaled) as fp16
#pragma unroll
    for (int mt = 0; mt < 2; mt++) {
        int r0 = m0 + wm * 32 + mt * 16 + g;
        int r1 = r0 + 8;
#pragma unroll
        for (int nt = 0; nt < 8; nt++) {
            int col = wn * 64 + nt * 8 + tg * 2;
            if (r0 < nN) {
                __half2 o = __floats2half2_rn(acc[mt][nt][0], acc[mt][nt][1]);
                *(__half2*)(g_h16 + (size_t)r0 * OUT_DIM + col) = o;
            }
            if (r1 < nN) {
                __half2 o = __floats2half2_rn(acc[mt][nt][2], acc[mt][nt][3]);
                *(__half2*)(g_h16 + (size_t)r1 * OUT_DIM + col) = o;
            }
        }
    }
}

// ---------------- fused aggregate + finalize (warp per node, 4-deep batching) ----
__device__ __forceinline__ void acc_row(float4& a, uint2 raw, float d) {
    __half2* h = (__half2*)&raw;
    float2 f0 = __half22float2(h[0]);
    float2 f1 = __half22float2(h[1]);
    a.x += f0.x * d; a.y += f0.y * d;
    a.z += f1.x * d; a.w += f1.y * d;
}

__global__ void __launch_bounds__(256) aggregate_kernel(
    float* __restrict__ out, const float* __restrict__ bg, int nN) {
    int w    = (int)((blockIdx.x * (unsigned)blockDim.x + threadIdx.x) >> 5);
    int lane = threadIdx.x & 31;
    if (w >= nN) return;

    int beg = g_rowptr[w];
    int end = g_rowptr[w + 1];
    float dw = g_dinv[w];

    // self loop message: dinv[w] * h[w]
    float4 a = make_float4(0.f, 0.f, 0.f, 0.f);
    {
        uint2 raw = __ldg(&((const uint2*)(g_h16 + (size_t)w * OUT_DIM))[lane]);
        acc_row(a, raw, dw);
    }

    int e = beg;
    for (; e + 4 <= end; e += 4) {
        int s0 = __ldg(&g_srcs[e + 0]);
        int s1 = __ldg(&g_srcs[e + 1]);
        int s2 = __ldg(&g_srcs[e + 2]);
        int s3 = __ldg(&g_srcs[e + 3]);
        uint2 r0 = __ldg(&((const uint2*)(g_h16 + (size_t)s0 * OUT_DIM))[lane]);
        uint2 r1 = __ldg(&((const uint2*)(g_h16 + (size_t)s1 * OUT_DIM))[lane]);
        uint2 r2 = __ldg(&((const uint2*)(g_h16 + (size_t)s2 * OUT_DIM))[lane]);
        uint2 r3 = __ldg(&((const uint2*)(g_h16 + (size_t)s3 * OUT_DIM))[lane]);
        float d0 = __ldg(&g_dinv[s0]);
        float d1 = __ldg(&g_dinv[s1]);
        float d2 = __ldg(&g_dinv[s2]);
        float d3 = __ldg(&g_dinv[s3]);
        acc_row(a, r0, d0);
        acc_row(a, r1, d1);
        acc_row(a, r2, d2);
        acc_row(a, r3, d3);
    }
    for (; e < end; e++) {
        int s0 = __ldg(&g_srcs[e]);
        uint2 r0 = __ldg(&((const uint2*)(g_h16 + (size_t)s0 * OUT_DIM))[lane]);
        float d0 = __ldg(&g_dinv[s0]);
        acc_row(a, r0, d0);
    }

    float4 b = ((const float4*)bg)[lane];
    a.x = a.x * dw + b.x;
    a.y = a.y * dw + b.y;
    a.z = a.z * dw + b.z;
    a.w = a.w * dw + b.w;

    float ss = a.x * a.x + a.y * a.y + a.z * a.z + a.w * a.w;
#pragma unroll
    for (int o = 16; o > 0; o >>= 1) ss += __shfl_xor_sync(0xffffffffu, ss, o);
    float inv = 1.0f / fmaxf(sqrtf(ss), 1e-12f);
    a.x *= inv; a.y *= inv; a.z *= inv; a.w *= inv;
    ((float4*)(out + (size_t)w * OUT_DIM))[lane] = a;
}

// ---------------- launch (stream fork/join, capture-legal) ----------------
extern "C" void kernel_launch(void* const* d_in, const int* in_sizes, int n_in,
                              void* d_out, int out_size) {
    const float* x  = (const float*)d_in[0];
    const void*  ei = d_in[1];
    const float* Wp = (const float*)d_in[2];
    const float* Wg = (const float*)d_in[3];
    const float* bg = (const float*)d_in[4];
    float* out = (float*)d_out;

    const int nN = in_sizes[0] / IN_DIM;   // 100000
    const int nE = in_sizes[1] / 2;        // 1600000
    const int nScanBlocks = (nN + 255) / 256;

    static cudaStream_t s2;
    static cudaEvent_t evF, evJ;
    static bool inited = false;
    if (!inited) {
        cudaStreamCreateWithFlags(&s2, cudaStreamNonBlocking);
        cudaEventCreateWithFlags(&evF, cudaEventDisableTiming);
        cudaEventCreateWithFlags(&evJ, cudaEventDisableTiming);
        inited = true;
    }

    // fork: CSR chain on s2, GEMM chain on default stream
    cudaEventRecord(evF, 0);
    cudaStreamWaitEvent(s2, evF, 0);

    detect_kernel<<<1, 32, 0, s2>>>(ei);
    zero_cnt_kernel<<<(nN + 255) / 256, 256, 0, s2>>>(nN);
    hist_kernel<<<(nE + 255) / 256, 256, 0, s2>>>(ei, nE);
    scanA_kernel<<<nScanBlocks, 256, 0, s2>>>(nN);
    scanB_kernel<<<1, 512, 0, s2>>>(nScanBlocks);
    scanC_kernel<<<(nN + 255) / 256, 256, 0, s2>>>(nN, nE);
    permute_kernel<<<(nE + 255) / 256, 256, 0, s2>>>(ei, nE);
    cudaEventRecord(evJ, s2);

    wc_kernel<<<OUT_DIM, 256>>>(Wp, Wg);
    gemm_mma_kernel<<<(nN + 127) / 128, 256>>>(x, nN);

    // join
    cudaStreamWaitEvent(0, evJ, 0);

    long long agg_threads = (long long)nN * 32;
    int agg_blocks = (int)((agg_threads + 255) / 256);
    aggregate_kernel<<<agg_blocks, 256>>>(out, bg, nN);
}

// round 9
// speedup vs baseline: 1.2550x; 1.0308x over previous
#include <cuda_runtime.h>
#include <cuda_bf16.h>
#include <cuda_fp16.h>
#include <cstdint>
#include <cstddef>

#define N_NODES 100000
#define N_EDGES 1600000
#define IN_DIM  256
#define OUT_DIM 128

// ---------------- scratch (no cudaMalloc allowed) ----------------
__device__ __half g_h16[(size_t)N_NODES * OUT_DIM]; // h (unscaled, fp16)  (25.6 MB)
__device__ uint32_t g_wcb[32768];                   // Wc as tf32 bits, [ch][n][kloc]
__device__ float g_dinv[N_NODES];                   // 1/sqrt(deg)
__device__ int   g_cnt[N_NODES];                    // in-degree (edges only)
__device__ int   g_cur[N_NODES];                    // scatter cursors
__device__ int   g_rowptr[N_NODES + 1];             // CSR row pointers (by target)
__device__ int   g_srcs[N_EDGES];                   // sorted-by-target source ids
__device__ int   g_incl[N_NODES];                   // per-chunk inclusive scans
__device__ int   g_bsum[512];                       // block sums for scan
__device__ int   g_is64;                            // edge_index dtype flag

__device__ __forceinline__ uint32_t f32_to_tf32(float f) {
    uint32_t u;
    asm("cvt.rna.tf32.f32 %0, %1;" : "=r"(u) : "f"(f));
    return u;
}

// ---------------- dtype detection (int64 vs int32 edge_index) ----------------
__global__ void detect_kernel(const void* __restrict__ ei) {
    if (threadIdx.x == 0 && blockIdx.x == 0) {
        const long long* p = (const long long*)ei;
        int is64 = 1;
        for (int i = 0; i < 8; i++) {
            long long v = p[i];
            if (v < 0 || v >= N_NODES) { is64 = 0; break; }
        }
        g_is64 = is64;
    }
}

__device__ __forceinline__ int load_idx(const void* __restrict__ ei, long long i, int is64) {
    if (is64) return (int)((const long long*)ei)[i];
    return ((const int*)ei)[i];
}

// ---------------- Wc = Wg @ Wp, converted to tf32 bits ----------------
// layout (u32): [ch][n][kloc]  ch = k>>5, kloc = k&31
__global__ void wc_kernel(const float* __restrict__ Wp, const float* __restrict__ Wg) {
    __shared__ float sWg[OUT_DIM];
    const int o2 = blockIdx.x;     // 0..127 (output row n)
    const int i  = threadIdx.x;    // 0..255 (k)
    if (i < OUT_DIM) sWg[i] = Wg[o2 * OUT_DIM + i];
    __syncthreads();
    float acc = 0.f;
#pragma unroll 8
    for (int o = 0; o < OUT_DIM; o++)
        acc += sWg[o] * Wp[o * IN_DIM + i];
    g_wcb[(i >> 5) * 4096 + o2 * 32 + (i & 31)] = f32_to_tf32(acc);
}

// ---------------- CSR build ----------------
__global__ void zero_cnt_kernel(int nN) {
    int i = blockIdx.x * blockDim.x + threadIdx.x;
    if (i < nN) g_cnt[i] = 0;
}

__global__ void hist_kernel(const void* __restrict__ ei, int nE) {
    int e = blockIdx.x * blockDim.x + threadIdx.x;
    if (e >= nE) return;
    int c = load_idx(ei, (long long)nE + e, g_is64);   // col (target)
    atomicAdd(&g_cnt[c], 1);
}

__global__ void scanA_kernel(int nN) {
    __shared__ int s[256];
    int tid = threadIdx.x;
    int i = blockIdx.x * 256 + tid;
    int v = (i < nN) ? g_cnt[i] : 0;
    s[tid] = v;
    __syncthreads();
#pragma unroll
    for (int o = 1; o < 256; o <<= 1) {
        int t = (tid >= o) ? s[tid - o] : 0;
        __syncthreads();
        s[tid] += t;
        __syncthreads();
    }
    if (i < nN) g_incl[i] = s[tid];
    if (tid == 255) g_bsum[blockIdx.x] = s[255];
}

__global__ void scanB_kernel(int nb) {
    __shared__ int s[512];
    int tid = threadIdx.x;
    int v = (tid < nb) ? g_bsum[tid] : 0;
    s[tid] = v;
    __syncthreads();
#pragma unroll
    for (int o = 1; o < 512; o <<= 1) {
        int t = (tid >= o) ? s[tid - o] : 0;
        __syncthreads();
        s[tid] += t;
        __syncthreads();
    }
    if (tid < nb) g_bsum[tid] = s[tid] - v;   // exclusive
}

__global__ void scanC_kernel(int nN, int nE) {
    int i = blockIdx.x * blockDim.x + threadIdx.x;
    if (i >= nN) return;
    int incl = g_incl[i] + g_bsum[i >> 8];
    g_rowptr[i + 1] = incl;
    int cnt = g_cnt[i];
    g_cur[i] = incl - cnt;                    // exclusive offset
    g_dinv[i] = rsqrtf((float)(cnt + 1));     // +1 for self loop
    if (i == 0) g_rowptr[0] = 0;
}

__global__ void permute_kernel(const void* __restrict__ ei, int nE) {
    int e = blockIdx.x * blockDim.x + threadIdx.x;
    if (e >= nE) return;
    int is64 = g_is64;
    int r = load_idx(ei, e, is64);                     // row (source)
    int c = load_idx(ei, (long long)nE + e, is64);     // col (target)
    int p = atomicAdd(&g_cur[c], 1);
    g_srcs[p] = r;
}

// ---------------- GEMM via mma.sync tf32: h = x @ Wc^T (unscaled) --------------
// CTA tile 128(M) x 128(N), K=256 in chunks of 32. 8 warps = 4(M) x 2(N).
// Warp tile 32x64 = 2 m16-tiles x 8 n8-tiles, k8 per MMA.
#define KC 32
#define SROW2 36   // u32 per smem row: 32 data + 4 pad (144B stride)

__device__ __forceinline__ void mma_tf32(float* c, const uint32_t* a, uint32_t b0, uint32_t b1) {
    asm volatile(
        "mma.sync.aligned.m16n8k8.row.col.f32.tf32.tf32.f32 "
        "{%0,%1,%2,%3}, {%4,%5,%6,%7}, {%8,%9}, {%0,%1,%2,%3};"
        : "+f"(c[0]), "+f"(c[1]), "+f"(c[2]), "+f"(c[3])
        : "r"(a[0]), "r"(a[1]), "r"(a[2]), "r"(a[3]), "r"(b0), "r"(b1));
}

__global__ void __launch_bounds__(256) gemm_mma_kernel(const float* __restrict__ x, int nN) {
    __shared__ __align__(16) uint32_t sa[128 * SROW2];
    __shared__ __align__(16) uint32_t sb[128 * SROW2];

    const int tid  = threadIdx.x;
    const int wid  = tid >> 5;
    const int lane = tid & 31;
    const int g    = lane >> 2;   // groupID
    const int tg   = lane & 3;    // thread in group
    const int wm   = wid >> 1;    // 0..3  -> m offset 32*wm
    const int wn   = wid & 1;     // 0..1  -> n offset 64*wn
    const int m0   = blockIdx.x * 128;

    float acc[2][8][4];
#pragma unroll
    for (int mt = 0; mt < 2; mt++)
#pragma unroll
        for (int nt = 0; nt < 8; nt++)
#pragma unroll
            for (int j = 0; j < 4; j++) acc[mt][nt][j] = 0.f;

    for (int ch = 0; ch < IN_DIM / KC; ch++) {
        const int kk = ch * KC;
        // stage A (x rows, f32 -> tf32) : 128 x 32, 1024 float4, 4/thread
#pragma unroll
        for (int i = 0; i < 4; i++) {
            int idx = tid + i * 256;
            int row = idx >> 3;          // 0..127
            int q   = idx & 7;           // float4 index within 32 k
            int gm  = m0 + row;
            float4 v = make_float4(0.f, 0.f, 0.f, 0.f);
            if (gm < nN) v = __ldg((const float4*)(x + (size_t)gm * IN_DIM + kk + q * 4));
            uint4 t;
            t.x = f32_to_tf32(v.x);
            t.y = f32_to_tf32(v.y);
            t.z = f32_to_tf32(v.z);
            t.w = f32_to_tf32(v.w);
            *(uint4*)&sa[row * SROW2 + q * 4] = t;
        }
        // stage B: raw copy of pre-converted tf32 chunk (1024 uint4)
        {
            const uint4* bsrc = (const uint4*)(g_wcb + ch * 4096);
#pragma unroll
            for (int i = 0; i < 4; i++) {
                int idx = tid + i * 256;
                int n   = idx >> 3;
                int q   = idx & 7;
                *(uint4*)&sb[n * SROW2 + q * 4] = __ldg(&bsrc[idx]);
            }
        }
        __syncthreads();

#pragma unroll
        for (int ks = 0; ks < KC / 8; ks++) {
            const int kb = ks * 8;
            uint32_t a[2][4];
#pragma unroll
            for (int mt = 0; mt < 2; mt++) {
                int r0 = (wm * 32 + mt * 16 + g) * SROW2 + kb + tg;
                int r1 = (wm * 32 + mt * 16 + g + 8) * SROW2 + kb + tg;
                a[mt][0] = sa[r0];
                a[mt][1] = sa[r1];
                a[mt][2] = sa[r0 + 4];
                a[mt][3] = sa[r1 + 4];
            }
#pragma unroll
            for (int nt = 0; nt < 8; nt++) {
                int n = wn * 64 + nt * 8 + g;
                int o = n * SROW2 + kb + tg;
                uint32_t b0 = sb[o], b1 = sb[o + 4];
#pragma unroll
                for (int mt = 0; mt < 2; mt++)
                    mma_tf32(acc[mt][nt], a[mt], b0, b1);
            }
        }
        __syncthreads();
    }

    // epilogue: store h (unscaled) as fp16
#pragma unroll
    for (int mt = 0; mt < 2; mt++) {
        int r0 = m0 + wm * 32 + mt * 16 + g;
        int r1 = r0 + 8;
#pragma unroll
        for (int nt = 0; nt < 8; nt++) {
            int col = wn * 64 + nt * 8 + tg * 2;
            if (r0 < nN) {
                __half2 o = __floats2half2_rn(acc[mt][nt][0], acc[mt][nt][1]);
                *(__half2*)(g_h16 + (size_t)r0 * OUT_DIM + col) = o;
            }
            if (r1 < nN) {
                __half2 o = __floats2half2_rn(acc[mt][nt][2], acc[mt][nt][3]);
                *(__half2*)(g_h16 + (size_t)r1 * OUT_DIM + col) = o;
            }
        }
    }
}

// ---------------- fused aggregate + finalize (warp per node, 8-deep batching) ----
__device__ __forceinline__ void acc_row(float4& a, uint2 raw, float d) {
    __half2* h = (__half2*)&raw;
    float2 f0 = __half22float2(h[0]);
    float2 f1 = __half22float2(h[1]);
    a.x += f0.x * d; a.y += f0.y * d;
    a.z += f1.x * d; a.w += f1.y * d;
}

__global__ void __launch_bounds__(256) aggregate_kernel(
    float* __restrict__ out, const float* __restrict__ bg, int nN) {
    int w    = (int)((blockIdx.x * (unsigned)blockDim.x + threadIdx.x) >> 5);
    int lane = threadIdx.x & 31;
    if (w >= nN) return;

    int beg = g_rowptr[w];
    int end = g_rowptr[w + 1];
    float dw = g_dinv[w];

    // self loop message: dinv[w] * h[w]
    float4 a = make_float4(0.f, 0.f, 0.f, 0.f);
    {
        uint2 raw = __ldg(&((const uint2*)(g_h16 + (size_t)w * OUT_DIM))[lane]);
        acc_row(a, raw, dw);
    }

    int e = beg;
    for (; e + 8 <= end; e += 8) {
        int s[8];
#pragma unroll
        for (int j = 0; j < 8; j++) s[j] = __ldg(&g_srcs[e + j]);
        uint2 r[8];
#pragma unroll
        for (int j = 0; j < 8; j++)
            r[j] = __ldg(&((const uint2*)(g_h16 + (size_t)s[j] * OUT_DIM))[lane]);
        float d[8];
#pragma unroll
        for (int j = 0; j < 8; j++) d[j] = __ldg(&g_dinv[s[j]]);
#pragma unroll
        for (int j = 0; j < 8; j++) acc_row(a, r[j], d[j]);
    }
    for (; e + 4 <= end; e += 4) {
        int s0 = __ldg(&g_srcs[e + 0]);
        int s1 = __ldg(&g_srcs[e + 1]);
        int s2 = __ldg(&g_srcs[e + 2]);
        int s3 = __ldg(&g_srcs[e + 3]);
        uint2 r0 = __ldg(&((const uint2*)(g_h16 + (size_t)s0 * OUT_DIM))[lane]);
        uint2 r1 = __ldg(&((const uint2*)(g_h16 + (size_t)s1 * OUT_DIM))[lane]);
        uint2 r2 = __ldg(&((const uint2*)(g_h16 + (size_t)s2 * OUT_DIM))[lane]);
        uint2 r3 = __ldg(&((const uint2*)(g_h16 + (size_t)s3 * OUT_DIM))[lane]);
        float d0 = __ldg(&g_dinv[s0]);
        float d1 = __ldg(&g_dinv[s1]);
        float d2 = __ldg(&g_dinv[s2]);
        float d3 = __ldg(&g_dinv[s3]);
        acc_row(a, r0, d0);
        acc_row(a, r1, d1);
        acc_row(a, r2, d2);
        acc_row(a, r3, d3);
    }
    for (; e < end; e++) {
        int s0 = __ldg(&g_srcs[e]);
        uint2 r0 = __ldg(&((const uint2*)(g_h16 + (size_t)s0 * OUT_DIM))[lane]);
        float d0 = __ldg(&g_dinv[s0]);
        acc_row(a, r0, d0);
    }

    float4 b = ((const float4*)bg)[lane];
    a.x = a.x * dw + b.x;
    a.y = a.y * dw + b.y;
    a.z = a.z * dw + b.z;
    a.w = a.w * dw + b.w;

    float ss = a.x * a.x + a.y * a.y + a.z * a.z + a.w * a.w;
#pragma unroll
    for (int o = 16; o > 0; o >>= 1) ss += __shfl_xor_sync(0xffffffffu, ss, o);
    float inv = 1.0f / fmaxf(sqrtf(ss), 1e-12f);
    a.x *= inv; a.y *= inv; a.z *= inv; a.w *= inv;
    ((float4*)(out + (size_t)w * OUT_DIM))[lane] = a;
}

// ---------------- launch (stream fork/join, capture-legal) ----------------
extern "C" void kernel_launch(void* const* d_in, const int* in_sizes, int n_in,
                              void* d_out, int out_size) {
    const float* x  = (const float*)d_in[0];
    const void*  ei = d_in[1];
    const float* Wp = (const float*)d_in[2];
    const float* Wg = (const float*)d_in[3];
    const float* bg = (const float*)d_in[4];
    float* out = (float*)d_out;

    const int nN = in_sizes[0] / IN_DIM;   // 100000
    const int nE = in_sizes[1] / 2;        // 1600000
    const int nScanBlocks = (nN + 255) / 256;

    static cudaStream_t s2;
    static cudaEvent_t evF, evJ;
    static bool inited = false;
    if (!inited) {
        cudaStreamCreateWithFlags(&s2, cudaStreamNonBlocking);
        cudaEventCreateWithFlags(&evF, cudaEventDisableTiming);
        cudaEventCreateWithFlags(&evJ, cudaEventDisableTiming);
        inited = true;
    }

    // fork: CSR chain on s2, GEMM chain on default stream
    cudaEventRecord(evF, 0);
    cudaStreamWaitEvent(s2, evF, 0);

    detect_kernel<<<1, 32, 0, s2>>>(ei);
    zero_cnt_kernel<<<(nN + 255) / 256, 256, 0, s2>>>(nN);
    hist_kernel<<<(nE + 255) / 256, 256, 0, s2>>>(ei, nE);
    scanA_kernel<<<nScanBlocks, 256, 0, s2>>>(nN);
    scanB_kernel<<<1, 512, 0, s2>>>(nScanBlocks);
    scanC_kernel<<<(nN + 255) / 256, 256, 0, s2>>>(nN, nE);
    permute_kernel<<<(nE + 255) / 256, 256, 0, s2>>>(ei, nE);
    cudaEventRecord(evJ, s2);

    wc_kernel<<<OUT_DIM, 256>>>(Wp, Wg);
    gemm_mma_kernel<<<(nN + 127) / 128, 256>>>(x, nN);

    // join
    cudaStreamWaitEvent(0, evJ, 0);

    long long agg_threads = (long long)nN * 32;
    int agg_blocks = (int)((agg_threads + 255) / 256);
    aggregate_kernel<<<agg_blocks, 256>>>(out, bg, nN);
}

// round 10
// speedup vs baseline: 1.3433x; 1.0704x over previous
#include <cuda_runtime.h>
#include <cuda_bf16.h>
#include <cuda_fp16.h>
#include <cstdint>
#include <cstddef>

#define N_NODES 100000
#define N_EDGES 1600000
#define IN_DIM  256
#define OUT_DIM 128

// ---------------- scratch (no cudaMalloc allowed) ----------------
__device__ __half g_h16[(size_t)N_NODES * OUT_DIM]; // h (unscaled, fp16)  (25.6 MB)
__device__ uint32_t g_wcb[32768];                   // Wc as tf32 bits, [ch][n][kloc]
__device__ float g_dinv[N_NODES];                   // 1/sqrt(deg)
__device__ int   g_cnt[N_NODES];                    // in-degree (edges only)
__device__ int   g_cur[N_NODES];                    // scatter cursors
__device__ int   g_rowptr[N_NODES + 1];             // CSR row pointers (by target)
__device__ int   g_srcs[N_EDGES];                   // sorted-by-target source ids
__device__ int   g_incl[N_NODES];                   // per-chunk inclusive scans
__device__ int   g_bsum[512];                       // block sums for scan
__device__ int   g_is64;                            // edge_index dtype flag

__device__ __forceinline__ uint32_t f32_to_tf32(float f) {
    uint32_t u;
    asm("cvt.rna.tf32.f32 %0, %1;" : "=r"(u) : "f"(f));
    return u;
}

__device__ __forceinline__ uint32_t smem_u32(const void* p) {
    uint32_t a;
    asm("{ .reg .u64 t; cvta.to.shared.u64 t, %1; cvt.u32.u64 %0, t; }" : "=r"(a) : "l"(p));
    return a;
}

__device__ __forceinline__ void cp16(uint32_t dst, const void* src, bool pred) {
    int sz = pred ? 16 : 0;
    asm volatile("cp.async.ca.shared.global [%0], [%1], 16, %2;"
                 :: "r"(dst), "l"(src), "r"(sz) : "memory");
}

// ---------------- dtype detection (int64 vs int32 edge_index) ----------------
__global__ void detect_kernel(const void* __restrict__ ei) {
    if (threadIdx.x == 0 && blockIdx.x == 0) {
        const long long* p = (const long long*)ei;
        int is64 = 1;
        for (int i = 0; i < 8; i++) {
            long long v = p[i];
            if (v < 0 || v >= N_NODES) { is64 = 0; break; }
        }
        g_is64 = is64;
    }
}

__device__ __forceinline__ int load_idx(const void* __restrict__ ei, long long i, int is64) {
    if (is64) return (int)((const long long*)ei)[i];
    return ((const int*)ei)[i];
}

// ---------------- Wc = Wg @ Wp, converted to tf32 bits ----------------
// layout (u32): [ch][n][kloc]  ch = k>>5, kloc = k&31
__global__ void wc_kernel(const float* __restrict__ Wp, const float* __restrict__ Wg) {
    __shared__ float sWg[OUT_DIM];
    const int o2 = blockIdx.x;     // 0..127 (output row n)
    const int i  = threadIdx.x;    // 0..255 (k)
    if (i < OUT_DIM) sWg[i] = Wg[o2 * OUT_DIM + i];
    __syncthreads();
    float acc = 0.f;
#pragma unroll 8
    for (int o = 0; o < OUT_DIM; o++)
        acc += sWg[o] * Wp[o * IN_DIM + i];
    g_wcb[(i >> 5) * 4096 + o2 * 32 + (i & 31)] = f32_to_tf32(acc);
}

// ---------------- CSR build ----------------
__global__ void zero_cnt_kernel(int nN) {
    int i = blockIdx.x * blockDim.x + threadIdx.x;
    if (i < nN) g_cnt[i] = 0;
}

__global__ void hist_kernel(const void* __restrict__ ei, int nE) {
    int e = blockIdx.x * blockDim.x + threadIdx.x;
    if (e >= nE) return;
    int c = load_idx(ei, (long long)nE + e, g_is64);   // col (target)
    atomicAdd(&g_cnt[c], 1);
}

__global__ void scanA_kernel(int nN) {
    __shared__ int s[256];
    int tid = threadIdx.x;
    int i = blockIdx.x * 256 + tid;
    int v = (i < nN) ? g_cnt[i] : 0;
    s[tid] = v;
    __syncthreads();
#pragma unroll
    for (int o = 1; o < 256; o <<= 1) {
        int t = (tid >= o) ? s[tid - o] : 0;
        __syncthreads();
        s[tid] += t;
        __syncthreads();
    }
    if (i < nN) g_incl[i] = s[tid];
    if (tid == 255) g_bsum[blockIdx.x] = s[255];
}

__global__ void scanB_kernel(int nb) {
    __shared__ int s[512];
    int tid = threadIdx.x;
    int v = (tid < nb) ? g_bsum[tid] : 0;
    s[tid] = v;
    __syncthreads();
#pragma unroll
    for (int o = 1; o < 512; o <<= 1) {
        int t = (tid >= o) ? s[tid - o] : 0;
        __syncthreads();
        s[tid] += t;
        __syncthreads();
    }
    if (tid < nb) g_bsum[tid] = s[tid] - v;   // exclusive
}

__global__ void scanC_kernel(int nN, int nE) {
    int i = blockIdx.x * blockDim.x + threadIdx.x;
    if (i >= nN) return;
    int incl = g_incl[i] + g_bsum[i >> 8];
    g_rowptr[i + 1] = incl;
    int cnt = g_cnt[i];
    g_cur[i] = incl - cnt;                    // exclusive offset
    g_dinv[i] = rsqrtf((float)(cnt + 1));     // +1 for self loop
    if (i == 0) g_rowptr[0] = 0;
}

__global__ void permute_kernel(const void* __restrict__ ei, int nE) {
    int e = blockIdx.x * blockDim.x + threadIdx.x;
    if (e >= nE) return;
    int is64 = g_is64;
    int r = load_idx(ei, e, is64);                     // row (source)
    int c = load_idx(ei, (long long)nE + e, is64);     // col (target)
    int p = atomicAdd(&g_cur[c], 1);
    g_srcs[p] = r;
}

// ---------------- GEMM via mma.sync tf32 + cp.async pipeline -------------------
// CTA tile 128(M) x 128(N), K=256 in 8 chunks of 32. 8 warps = 4(M) x 2(N).
// Double-buffered dynamic smem: A raw fp32 (cvt at fragment load), B tf32 bits.
#define KC 32
#define NCHUNK (IN_DIM / KC)
#define SROWA 36   // u32 per smem row: 32 data + 4 pad (144B stride)
#define ABUF_U32 (128 * SROWA)          // 4608
#define GEMM_SMEM_BYTES (4 * ABUF_U32 * 4)  // A0,A1,B0,B1 = 73728 B

__device__ __forceinline__ void mma_tf32(float* c, const uint32_t* a, uint32_t b0, uint32_t b1) {
    asm volatile(
        "mma.sync.aligned.m16n8k8.row.col.f32.tf32.tf32.f32 "
        "{%0,%1,%2,%3}, {%4,%5,%6,%7}, {%8,%9}, {%0,%1,%2,%3};"
        : "+f"(c[0]), "+f"(c[1]), "+f"(c[2]), "+f"(c[3])
        : "r"(a[0]), "r"(a[1]), "r"(a[2]), "r"(a[3]), "r"(b0), "r"(b1));
}

__device__ __forceinline__ void stage_chunk(uint32_t sbase, int buf, const float* __restrict__ x,
                                            int m0, int ch, int tid, int nN) {
    const int kk = ch * KC;
#pragma unroll
    for (int i = 0; i < 4; i++) {
        int idx = tid + i * 256;
        int row = idx >> 3, q = idx & 7;
        int gm  = m0 + row;
        uint32_t dA = sbase + (uint32_t)(buf * ABUF_U32 + row * SROWA + q * 4) * 4u;
        cp16(dA, x + (size_t)gm * IN_DIM + kk + q * 4, gm < nN);
    }
    const uint4* bsrc = (const uint4*)(g_wcb + ch * 4096);
#pragma unroll
    for (int i = 0; i < 4; i++) {
        int idx = tid + i * 256;
        int n = idx >> 3, q = idx & 7;
        uint32_t dB = sbase + (uint32_t)((2 + buf) * ABUF_U32 + n * SROWA + q * 4) * 4u;
        cp16(dB, bsrc + idx, true);
    }
}

__global__ void __launch_bounds__(256) gemm_mma_kernel(const float* __restrict__ x, int nN) {
    extern __shared__ uint32_t smemD[];
    uint32_t sbase = smem_u32(smemD);

    const int tid  = threadIdx.x;
    const int wid  = tid >> 5;
    const int lane = tid & 31;
    const int g    = lane >> 2;   // groupID
    const int tg   = lane & 3;    // thread in group
    const int wm   = wid >> 1;    // 0..3  -> m offset 32*wm
    const int wn   = wid & 1;     // 0..1  -> n offset 64*wn
    const int m0   = blockIdx.x * 128;

    float acc[2][8][4];
#pragma unroll
    for (int mt = 0; mt < 2; mt++)
#pragma unroll
        for (int nt = 0; nt < 8; nt++)
#pragma unroll
            for (int j = 0; j < 4; j++) acc[mt][nt][j] = 0.f;

    stage_chunk(sbase, 0, x, m0, 0, tid, nN);
    asm volatile("cp.async.commit_group;" ::: "memory");

    for (int ch = 0; ch < NCHUNK; ch++) {
        const int buf = ch & 1;
        if (ch + 1 < NCHUNK) {
            stage_chunk(sbase, buf ^ 1, x, m0, ch + 1, tid, nN);
            asm volatile("cp.async.commit_group;" ::: "memory");
            asm volatile("cp.async.wait_group 1;" ::: "memory");
        } else {
            asm volatile("cp.async.wait_group 0;" ::: "memory");
        }
        __syncthreads();

        const uint32_t* sa = smemD + buf * ABUF_U32;
        const uint32_t* sb = smemD + (2 + buf) * ABUF_U32;

#pragma unroll
        for (int ks = 0; ks < KC / 8; ks++) {
            const int kb = ks * 8;
            uint32_t a[2][4];
#pragma unroll
            for (int mt = 0; mt < 2; mt++) {
                int r0 = (wm * 32 + mt * 16 + g) * SROWA + kb + tg;
                int r1 = (wm * 32 + mt * 16 + g + 8) * SROWA + kb + tg;
                a[mt][0] = f32_to_tf32(__uint_as_float(sa[r0]));
                a[mt][1] = f32_to_tf32(__uint_as_float(sa[r1]));
                a[mt][2] = f32_to_tf32(__uint_as_float(sa[r0 + 4]));
                a[mt][3] = f32_to_tf32(__uint_as_float(sa[r1 + 4]));
            }
#pragma unroll
            for (int nt = 0; nt < 8; nt++) {
                int n = wn * 64 + nt * 8 + g;
                int o = n * SROWA + kb + tg;
                uint32_t b0 = sb[o], b1 = sb[o + 4];
#pragma unroll
                for (int mt = 0; mt < 2; mt++)
                    mma_tf32(acc[mt][nt], a[mt], b0, b1);
            }
        }
        __syncthreads();
    }

    // epilogue: store h (unscaled) as fp16
#pragma unroll
    for (int mt = 0; mt < 2; mt++) {
        int r0 = m0 + wm * 32 + mt * 16 + g;
        int r1 = r0 + 8;
#pragma unroll
        for (int nt = 0; nt < 8; nt++) {
            int col = wn * 64 + nt * 8 + tg * 2;
            if (r0 < nN) {
                __half2 o = __floats2half2_rn(acc[mt][nt][0], acc[mt][nt][1]);
                *(__half2*)(g_h16 + (size_t)r0 * OUT_DIM + col) = o;
            }
            if (r1 < nN) {
                __half2 o = __floats2half2_rn(acc[mt][nt][2], acc[mt][nt][3]);
                *(__half2*)(g_h16 + (size_t)r1 * OUT_DIM + col) = o;
            }
        }
    }
}

// ---------------- fused aggregate + finalize (paired-edge half-warp gather) ------
// Warp owns one node. Lanes 0-15 fetch even items, 16-31 odd items (uint4 = 8 fp16
// features per lane, 16 lanes per row). Item 0 = self loop, item j>0 = edge j-1.
__device__ __forceinline__ void accu4(float* a, uint4 raw, float d) {
    __half2* h = (__half2*)&raw;
#pragma unroll
    for (int k = 0; k < 4; k++) {
        float2 f = __half22float2(h[k]);
        a[2 * k]     += f.x * d;
        a[2 * k + 1] += f.y * d;
    }
}

__global__ void __launch_bounds__(256) aggregate_kernel(
    float* __restrict__ out, const float* __restrict__ bg, int nN) {
    int w    = (int)((blockIdx.x * (unsigned)blockDim.x + threadIdx.x) >> 5);
    int lane = threadIdx.x & 31;
    int hl   = lane >> 4;          // half id: item parity
    int sl   = lane & 15;          // sublane: feature group 8*sl..8*sl+7
    if (w >= nN) return;

    int beg = g_rowptr[w];
    int end = g_rowptr[w + 1];
    int nItems = 1 + (end - beg);  // self + edges
    float dw = g_dinv[w];

    float a[8] = {0.f, 0.f, 0.f, 0.f, 0.f, 0.f, 0.f, 0.f};

    int j = hl;
    // batched: 4 items per half per round (8 items/round warp-wide)
    for (; j + 6 < nItems; j += 8) {
        int rows[4];
#pragma unroll
        for (int t = 0; t < 4; t++) {
            int jj = j + 2 * t;
            rows[t] = (jj == 0) ? w : __ldg(&g_srcs[beg + jj - 1]);
        }
        uint4 rr[4];
#pragma unroll
        for (int t = 0; t < 4; t++)
            rr[t] = __ldg((const uint4*)(g_h16 + (size_t)rows[t] * OUT_DIM) + sl);
        float dd[4];
#pragma unroll
        for (int t = 0; t < 4; t++) dd[t] = __ldg(&g_dinv[rows[t]]);
#pragma unroll
        for (int t = 0; t < 4; t++) accu4(a, rr[t], dd[t]);
    }
    for (; j < nItems; j += 2) {
        int row = (j == 0) ? w : __ldg(&g_srcs[beg + j - 1]);
        uint4 r = __ldg((const uint4*)(g_h16 + (size_t)row * OUT_DIM) + sl);
        float d = __ldg(&g_dinv[row]);
        accu4(a, r, d);
    }

    // combine the two halves (same feature group in lanes sl and sl+16)
#pragma unroll
    for (int k = 0; k < 8; k++) a[k] += __shfl_xor_sync(0xffffffffu, a[k], 16);

    // bias + dinv scale
    float4 b0 = ((const float4*)bg)[sl * 2];
    float4 b1 = ((const float4*)bg)[sl * 2 + 1];
    a[0] = a[0] * dw + b0.x;  a[1] = a[1] * dw + b0.y;
    a[2] = a[2] * dw + b0.z;  a[3] = a[3] * dw + b0.w;
    a[4] = a[4] * dw + b1.x;  a[5] = a[5] * dw + b1.y;
    a[6] = a[6] * dw + b1.z;  a[7] = a[7] * dw + b1.w;

    float ss = 0.f;
#pragma unroll
    for (int k = 0; k < 8; k++) ss += a[k] * a[k];
#pragma unroll
    for (int o = 8; o > 0; o >>= 1) ss += __shfl_xor_sync(0xffffffffu, ss, o);
    float inv = 1.0f / fmaxf(sqrtf(ss), 1e-12f);

    // each lane stores one float4: half 0 -> features 8sl..+3, half 1 -> 8sl+4..+7
    float4 v = (hl == 0)
        ? make_float4(a[0] * inv, a[1] * inv, a[2] * inv, a[3] * inv)
        : make_float4(a[4] * inv, a[5] * inv, a[6] * inv, a[7] * inv);
    *(float4*)(out + (size_t)w * OUT_DIM + sl * 8 + hl * 4) = v;
}

// ---------------- launch (stream fork/join, capture-legal) ----------------
extern "C" void kernel_launch(void* const* d_in, const int* in_sizes, int n_in,
                              void* d_out, int out_size) {
    const float* x  = (const float*)d_in[0];
    const void*  ei = d_in[1];
    const float* Wp = (const float*)d_in[2];
    const float* Wg = (const float*)d_in[3];
    const float* bg = (const float*)d_in[4];
    float* out = (float*)d_out;

    const int nN = in_sizes[0] / IN_DIM;   // 100000
    const int nE = in_sizes[1] / 2;        // 1600000
    const int nScanBlocks = (nN + 255) / 256;

    static cudaStream_t s2;
    static cudaEvent_t evF, evJ;
    static bool inited = false;
    if (!inited) {
        cudaStreamCreateWithFlags(&s2, cudaStreamNonBlocking);
        cudaEventCreateWithFlags(&evF, cudaEventDisableTiming);
        cudaEventCreateWithFlags(&evJ, cudaEventDisableTiming);
        cudaFuncSetAttribute(gemm_mma_kernel,
                             cudaFuncAttributeMaxDynamicSharedMemorySize,
                             GEMM_SMEM_BYTES);
        inited = true;
    }

    // fork: CSR chain on s2, GEMM chain on default stream
    cudaEventRecord(evF, 0);
    cudaStreamWaitEvent(s2, evF, 0);

    detect_kernel<<<1, 32, 0, s2>>>(ei);
    zero_cnt_kernel<<<(nN + 255) / 256, 256, 0, s2>>>(nN);
    hist_kernel<<<(nE + 255) / 256, 256, 0, s2>>>(ei, nE);
    scanA_kernel<<<nScanBlocks, 256, 0, s2>>>(nN);
    scanB_kernel<<<1, 512, 0, s2>>>(nScanBlocks);
    scanC_kernel<<<(nN + 255) / 256, 256, 0, s2>>>(nN, nE);
    permute_kernel<<<(nE + 255) / 256, 256, 0, s2>>>(ei, nE);
    cudaEventRecord(evJ, s2);

    wc_kernel<<<OUT_DIM, 256>>>(Wp, Wg);
    gemm_mma_kernel<<<(nN + 127) / 128, 256, GEMM_SMEM_BYTES>>>(x, nN);

    // join
    cudaStreamWaitEvent(0, evJ, 0);

    long long agg_threads = (long long)nN * 32;
    int agg_blocks = (int)((agg_threads + 255) / 256);
    aggregate_kernel<<<agg_blocks, 256>>>(out, bg, nN);
}